// round 12
// baseline (speedup 1.0000x reference)
#include <cuda_runtime.h>
#include <cuda_bf16.h>
#include <mma.h>
#include <cstdint>

using namespace nvcuda;

// Fused conv3x3(pad bottom/right)+bias*scale+maxpool2x2+clamp via WMMA (HMMA).
// D[M,16] = A[M,32] x B[32,16]; A = im2col(x) bf16-split (hi+lo), B = w*scale
// bf16-split; 3 passes Ahi*Bhi + Alo*Bhi + Ahi*Blo, f32 accum. m=4p+q puts each
// maxpool quad in 4 consecutive D rows -> pool via float4 smem reads.

#define ICN 3
#define IH  512
#define IW  512
#define CH  (IH * IW)
#define OCN 16
#define PHN 256
#define PWN 256

#define ALD 40                          // A smem row stride (bf16 elems), conflict-free LDSM
#define ATILE_B (16 * ALD * 2)          // 1280 B per m16 tile per split
#define A_HI_OFF 0
#define A_LO_OFF (16 * ATILE_B)         // 20480
#define B_HI_OFF (2 * 16 * ATILE_B)     // 40960
#define B_LO_OFF (B_HI_OFF + 32 * OCN * 2)   // +1024
#define SBS_OFF  (B_LO_OFF + 32 * OCN * 2)   // +1024
#define SM_BYTES (SBS_OFF + 64)

#define DLD 24                          // D smem ld (f32): 16B-aligned float4 rows
#define DTILE_F (16 * DLD)              // 384 floats (1536 B) per tile

__device__ __forceinline__ uint32_t bf2pack(float hi, float lo) {  // {lo|hi<<16}
    uint32_t r;
    asm("cvt.rn.bf16x2.f32 %0, %1, %2;" : "=r"(r) : "f"(hi), "f"(lo));
    return r;
}

__global__ __launch_bounds__(256)
void conv_wmma_kernel(const float* __restrict__ x,
                      const float* __restrict__ w,
                      const float* __restrict__ bias,
                      const float* __restrict__ scale,
                      float* __restrict__ out) {
    __shared__ __align__(16) uint8_t sm[SM_BYTES];
    __nv_bfloat16* Ahi = (__nv_bfloat16*)(sm + A_HI_OFF);
    __nv_bfloat16* Alo = (__nv_bfloat16*)(sm + A_LO_OFF);
    __nv_bfloat16* Bhi = (__nv_bfloat16*)(sm + B_HI_OFF);
    __nv_bfloat16* Blo = (__nv_bfloat16*)(sm + B_LO_OFF);
    float* sbs = (float*)(sm + SBS_OFF);
    float* Dsm = (float*)sm;            // aliases A region (A dead by then)

    const int u   = threadIdx.x;
    const int pw0 = blockIdx.x * 64;
    const int ph  = blockIdx.y;
    const int bi  = blockIdx.z;

    // ---- build B [k32][n16] (scale folded), bf16 hi/lo; bias' ----
    for (int e = u; e < 512; e += 256) {
        const int k = e >> 4, n = e & 15;
        const float val = (k < 27) ? w[n * 27 + k] * scale[n] : 0.0f;
        const __nv_bfloat16 h = __float2bfloat16(val);
        Bhi[k * 16 + n] = h;
        Blo[k * 16 + n] = __float2bfloat16(val - __bfloat162float(h));
    }
    if (u < OCN) sbs[u] = bias[u] * scale[u];

    // ---- build A: one conv px per thread. tile t=u>>4, row m=u&15, m=4p+q ----
    {
        const int t = u >> 4, m = u & 15;
        const int p = m >> 2, q = m & 3;
        const int pw = pw0 + t * 4 + p;
        const int oh = 2 * ph + (q >> 1);
        const int ow = 2 * pw + (q & 1);
        const bool rv1 = oh < IH - 1, rv2 = oh < IH - 2;
        const bool cv1 = ow < IW - 1, cv2 = ow < IW - 2;
        const float* bp = x + (size_t)bi * (ICN * CH) + (size_t)oh * IW + ow;

        float v[32];
#pragma unroll
        for (int k = 0; k < 32; k++) v[k] = 0.0f;
#pragma unroll
        for (int ic = 0; ic < ICN; ic++) {
            const float* cp = bp + ic * CH;
            v[ic * 9 + 0] = cp[0];
            if (cv1) v[ic * 9 + 1] = cp[1];
            if (cv2) v[ic * 9 + 2] = cp[2];
            if (rv1) {
                v[ic * 9 + 3] = cp[IW];
                if (cv1) v[ic * 9 + 4] = cp[IW + 1];
                if (cv2) v[ic * 9 + 5] = cp[IW + 2];
            }
            if (rv2) {
                v[ic * 9 + 6] = cp[2 * IW];
                if (cv1) v[ic * 9 + 7] = cp[2 * IW + 1];
                if (cv2) v[ic * 9 + 8] = cp[2 * IW + 2];
            }
        }

        uint32_t* Ahi32 = (uint32_t*)Ahi;
        uint32_t* Alo32 = (uint32_t*)Alo;
        const int b32 = t * (16 * ALD / 2) + m * (ALD / 2);
#pragma unroll
        for (int j = 0; j < 16; j++) {
            const float v0 = v[2 * j], v1 = v[2 * j + 1];
            const uint32_t h = bf2pack(v1, v0);
            const float h0 = __uint_as_float(h << 16);
            const float h1 = __uint_as_float(h & 0xFFFF0000u);
            Ahi32[b32 + j] = h;
            Alo32[b32 + j] = bf2pack(v1 - h1, v0 - h0);
        }
    }
    __syncthreads();

    // ---- WMMA: per warp 2 tiles x (2 k-chunks x 3 passes) ----
    const int wid = u >> 5;
    wmma::fragment<wmma::matrix_b, 16, 16, 16, __nv_bfloat16, wmma::row_major> fbh[2], fbl[2];
#pragma unroll
    for (int kc = 0; kc < 2; kc++) {
        wmma::load_matrix_sync(fbh[kc], Bhi + kc * 16 * 16, 16);
        wmma::load_matrix_sync(fbl[kc], Blo + kc * 16 * 16, 16);
    }

    wmma::fragment<wmma::accumulator, 16, 16, 16, float> acc[2];
#pragma unroll
    for (int ti = 0; ti < 2; ti++) {
        const int t = wid * 2 + ti;
        wmma::fill_fragment(acc[ti], 0.0f);
        const __nv_bfloat16* At_hi = Ahi + t * (16 * ALD);
        const __nv_bfloat16* At_lo = Alo + t * (16 * ALD);
        wmma::fragment<wmma::matrix_a, 16, 16, 16, __nv_bfloat16, wmma::row_major> fah, fal;
#pragma unroll
        for (int kc = 0; kc < 2; kc++) {
            wmma::load_matrix_sync(fah, At_hi + kc * 16, ALD);
            wmma::load_matrix_sync(fal, At_lo + kc * 16, ALD);
            wmma::mma_sync(acc[ti], fah, fbh[kc], acc[ti]);
            wmma::mma_sync(acc[ti], fal, fbh[kc], acc[ti]);
            wmma::mma_sync(acc[ti], fah, fbl[kc], acc[ti]);
        }
    }
    __syncthreads();   // all A reads done -> safe to alias D over A

#pragma unroll
    for (int ti = 0; ti < 2; ti++) {
        const int t = wid * 2 + ti;
        // col-major: Dsm[t][oc*DLD + m]
        wmma::store_matrix_sync(Dsm + t * DTILE_F, acc[ti], DLD, wmma::mem_col_major);
    }
    __syncthreads();

    // ---- pool 2x2 (rows 4p..4p+3) + bias' + clamp, float4-coalesced store ----
    {
        const int oc = u & 15, g = u >> 4;          // g = tile index
        const float4* Dp = (const float4*)(Dsm + g * DTILE_F + oc * DLD);
        const float bsv = sbs[oc];
        float4 res;
        float* r = &res.x;
#pragma unroll
        for (int i = 0; i < 4; i++) {
            const float4 qv = Dp[i];                // m = 4i..4i+3
            float mx = fmaxf(fmaxf(qv.x, qv.y), fmaxf(qv.z, qv.w));
            r[i] = fminf(fmaxf(mx + bsv, 0.0f), 1.0f);
        }
        float* op = out + (((size_t)(bi * OCN + oc)) * PHN + ph) * PWN + pw0 + g * 4;
        *(float4*)op = res;
    }
}

extern "C" void kernel_launch(void* const* d_in, const int* in_sizes, int n_in,
                              void* d_out, int out_size) {
    const float* x     = (const float*)d_in[0];
    const float* w     = (const float*)d_in[1];
    const float* bias  = (const float*)d_in[2];
    const float* scale = (const float*)d_in[3];
    float* out = (float*)d_out;

    const int B = in_sizes[0] / (ICN * IH * IW);   // 32

    dim3 block(256);
    dim3 grid(PWN / 64, PHN, B);                   // 4 x 256 x 32 = 32768 blocks
    conv_wmma_kernel<<<grid, block>>>(x, w, bias, scale, out);
}

// round 13
// speedup vs baseline: 1.3124x; 1.3124x over previous
#include <cuda_runtime.h>
#include <cuda_bf16.h>
#include <mma.h>
#include <cstdint>

using namespace nvcuda;

// Hybrid: fp32-pipe scalar kernel (proven 204.8us) + WMMA tensor-core kernel
// (proven 319us, rel_err 4.9e-6) running CONCURRENTLY on forked streams, work
// split by pooled row (alpha=0.80 scalar). Both persistent with limited grids
// (3 + 2 blocks/SM) so they co-reside and bind on different pipes (fma vs L1).

typedef unsigned long long ull;

#define OCN 16
#define ICN 3
#define IH 512
#define IW 512
#define PH 256
#define PW 256
#define CH (IH * IW)
#define NW (OCN * ICN * 9)

#define SGRID 444   // scalar persistent blocks (3/SM)
#define WGRID 296   // wmma persistent blocks (2/SM)

// ======================= scalar path (R9) =======================
#define OCG 2

struct Params {
    ull w2[NW];
    ull sc[OCN];
    ull bs[OCN];
};
__device__    Params g_stage;
__constant__  Params c_p;
__device__ float g_zpad[2 * CH + 6 * IW + 8];

__device__ __forceinline__ ull pack2(float a, float b) {
    ull r; asm("mov.b64 %0, {%1, %2};" : "=l"(r) : "f"(a), "f"(b)); return r;
}
__device__ __forceinline__ void unpack2(ull p, float& a, float& b) {
    asm("mov.b64 {%0, %1}, %2;" : "=f"(a), "=f"(b) : "l"(p));
}
__device__ __forceinline__ ull midpair(ull lo, ull hi) {
    ull r;
    asm("{\n\t.reg .b32 a, b, c, d;\n\t"
        "mov.b64 {a, b}, %1;\n\tmov.b64 {c, d}, %2;\n\tmov.b64 %0, {b, c};\n\t}"
        : "=l"(r) : "l"(lo), "l"(hi));
    return r;
}
__device__ __forceinline__ void fma2(ull& acc, ull a, ull b) {
    asm("fma.rn.f32x2 %0, %1, %2, %0;" : "+l"(acc) : "l"(a), "l"(b));
}
__device__ __forceinline__ ull fma2n(ull a, ull b, ull c) {
    ull d; asm("fma.rn.f32x2 %0, %1, %2, %3;" : "=l"(d) : "l"(a), "l"(b), "l"(c)); return d;
}

__global__ void prep_kernel(const float* __restrict__ w,
                            const float* __restrict__ bias,
                            const float* __restrict__ scale) {
    const int i = threadIdx.x;
    if (i < NW) { float v = w[i]; g_stage.w2[i] = pack2(v, v); }
    if (i < OCN) {
        float s = scale[i], bs = bias[i] * s;
        g_stage.sc[i] = pack2(s, s);
        g_stage.bs[i] = pack2(bs, bs);
    }
}

__global__ __launch_bounds__(128, 5)
void conv_scalar_kernel(const float* __restrict__ x,
                        float* __restrict__ out, int n_units) {
    const int tid = threadIdx.x;

    for (int u = blockIdx.x; u < n_units; u += SGRID) {
        const int ocbase = (u & 7) * OCG;
        const int g   = u >> 3;
        const int bi  = g >> 7;
        const int phb = g & 127;

        const int ih0 = phb * 4;
        const int iw0 = tid * 4;

        const float* base = x + (size_t)bi * (ICN * CH) + ih0 * IW + iw0;
        const bool  redge = (tid == 127);
        const bool  bok   = (phb != 127);
        const float* hi03 = redge ? g_zpad : (base + 4);
        const float* lo45 = bok   ? base   : g_zpad;
        const float* hi45 = (bok && !redge) ? (base + 4) : g_zpad;

        ull acc[OCG][4][2];
#pragma unroll
        for (int o = 0; o < OCG; o++)
#pragma unroll
            for (int r = 0; r < 4; r++) { acc[o][r][0] = 0ull; acc[o][r][1] = 0ull; }

#pragma unroll
        for (int ic = 0; ic < ICN; ic++) {
            ull p[6][5];
#pragma unroll
            for (int rr = 0; rr < 6; rr++) {
                const float* lp = (rr < 4) ? base : lo45;
                const float* hp = (rr < 4) ? hi03 : hi45;
                const ull L0 = *(const ull*)(lp + ic * CH + rr * IW);
                const ull L1 = *(const ull*)(lp + ic * CH + rr * IW + 2);
                const ull L2 = *(const ull*)(hp + ic * CH + rr * IW);
                p[rr][0] = L0;
                p[rr][1] = midpair(L0, L1);
                p[rr][2] = L1;
                p[rr][3] = midpair(L1, L2);
                p[rr][4] = L2;
            }
#pragma unroll
            for (int oc = 0; oc < OCG; oc++) {
                const ull* wp = &c_p.w2[((ocbase + oc) * ICN + ic) * 9];
#pragma unroll
                for (int kh = 0; kh < 3; kh++) {
#pragma unroll
                    for (int kw = 0; kw < 3; kw++) {
                        const ull w2 = wp[kh * 3 + kw];
#pragma unroll
                        for (int r = 0; r < 4; r++) {
                            fma2(acc[oc][r][0], p[kh + r][kw],     w2);
                            fma2(acc[oc][r][1], p[kh + r][kw + 2], w2);
                        }
                    }
                }
            }
        }

        const int ph0 = phb * 2;
#pragma unroll
        for (int oc = 0; oc < OCG; oc++) {
            const ull sc = c_p.sc[ocbase + oc];
            const ull bs = c_p.bs[ocbase + oc];
            float* orow = out + (((size_t)(bi * OCN + ocbase + oc)) * PH + ph0) * PW + 2 * tid;
#pragma unroll
            for (int pr = 0; pr < 2; pr++) {
                float m[2];
#pragma unroll
                for (int t = 0; t < 2; t++) {
                    float e0, e1, e2, e3;
                    ull y0 = fma2n(acc[oc][2 * pr + 0][t], sc, bs);
                    ull y1 = fma2n(acc[oc][2 * pr + 1][t], sc, bs);
                    unpack2(y0, e0, e1);
                    unpack2(y1, e2, e3);
                    m[t] = fminf(fmaxf(fmaxf(fmaxf(e0, e1), fmaxf(e2, e3)), 0.0f), 1.0f);
                }
                *(ull*)(orow + (size_t)pr * PW) = pack2(m[0], m[1]);
            }
        }
    }
}

// ======================= wmma path (R12) =======================
#define ALD 40
#define ATILE_B (16 * ALD * 2)
#define A_HI_OFF 0
#define A_LO_OFF (16 * ATILE_B)
#define B_HI_OFF (2 * 16 * ATILE_B)
#define B_LO_OFF (B_HI_OFF + 32 * OCN * 2)
#define SBS_OFF  (B_LO_OFF + 32 * OCN * 2)
#define SM_BYTES (SBS_OFF + 64)
#define DLD 24
#define DTILE_F (16 * DLD)

__device__ __forceinline__ uint32_t bf2pack(float hi, float lo) {
    uint32_t r; asm("cvt.rn.bf16x2.f32 %0, %1, %2;" : "=r"(r) : "f"(hi), "f"(lo)); return r;
}

__global__ __launch_bounds__(256)
void conv_wmma_kernel(const float* __restrict__ x,
                      const float* __restrict__ w,
                      const float* __restrict__ bias,
                      const float* __restrict__ scale,
                      float* __restrict__ out, int r0, int n_units) {
    __shared__ __align__(16) uint8_t sm[SM_BYTES];
    __nv_bfloat16* Ahi = (__nv_bfloat16*)(sm + A_HI_OFF);
    __nv_bfloat16* Alo = (__nv_bfloat16*)(sm + A_LO_OFF);
    __nv_bfloat16* Bhi = (__nv_bfloat16*)(sm + B_HI_OFF);
    __nv_bfloat16* Blo = (__nv_bfloat16*)(sm + B_LO_OFF);
    float* sbs = (float*)(sm + SBS_OFF);
    float* Dsm = (float*)sm;            // aliases A (A dead at epilogue)

    const int u = threadIdx.x;
    const int wid = u >> 5;

    for (int e = u; e < 512; e += 256) {
        const int k = e >> 4, n = e & 15;
        const float val = (k < 27) ? w[n * 27 + k] * scale[n] : 0.0f;
        const __nv_bfloat16 h = __float2bfloat16(val);
        Bhi[k * 16 + n] = h;
        Blo[k * 16 + n] = __float2bfloat16(val - __bfloat162float(h));
    }
    if (u < OCN) sbs[u] = bias[u] * scale[u];
    __syncthreads();

    wmma::fragment<wmma::matrix_b, 16, 16, 16, __nv_bfloat16, wmma::row_major> fbh[2], fbl[2];
#pragma unroll
    for (int kc = 0; kc < 2; kc++) {
        wmma::load_matrix_sync(fbh[kc], Bhi + kc * 16 * 16, 16);
        wmma::load_matrix_sync(fbl[kc], Blo + kc * 16 * 16, 16);
    }

    for (int it = blockIdx.x; it < n_units; it += WGRID) {
        const int cb = it & 3;
        const int r  = r0 + (it >> 2);
        const int bi = r >> 8;
        const int ph = r & 255;
        const int pw0 = cb * 64;

        __syncthreads();   // prior epilogue readers done before A overwrite

        // ---- build A (one conv px per thread) ----
        {
            const int t = u >> 4, m = u & 15;
            const int p = m >> 2, q = m & 3;
            const int pw = pw0 + t * 4 + p;
            const int oh = 2 * ph + (q >> 1);
            const int ow = 2 * pw + (q & 1);
            const bool rv1 = oh < IH - 1, rv2 = oh < IH - 2;
            const bool cv1 = ow < IW - 1, cv2 = ow < IW - 2;
            const float* bp = x + (size_t)bi * (ICN * CH) + (size_t)oh * IW + ow;

            float v[32];
#pragma unroll
            for (int k = 0; k < 32; k++) v[k] = 0.0f;
#pragma unroll
            for (int ic = 0; ic < ICN; ic++) {
                const float* cp = bp + ic * CH;
                v[ic * 9 + 0] = cp[0];
                if (cv1) v[ic * 9 + 1] = cp[1];
                if (cv2) v[ic * 9 + 2] = cp[2];
                if (rv1) {
                    v[ic * 9 + 3] = cp[IW];
                    if (cv1) v[ic * 9 + 4] = cp[IW + 1];
                    if (cv2) v[ic * 9 + 5] = cp[IW + 2];
                }
                if (rv2) {
                    v[ic * 9 + 6] = cp[2 * IW];
                    if (cv1) v[ic * 9 + 7] = cp[2 * IW + 1];
                    if (cv2) v[ic * 9 + 8] = cp[2 * IW + 2];
                }
            }
            uint32_t* Ahi32 = (uint32_t*)Ahi;
            uint32_t* Alo32 = (uint32_t*)Alo;
            const int b32 = t * (16 * ALD / 2) + m * (ALD / 2);
#pragma unroll
            for (int j = 0; j < 16; j++) {
                const float v0 = v[2 * j], v1 = v[2 * j + 1];
                const uint32_t h = bf2pack(v1, v0);
                const float h0 = __uint_as_float(h << 16);
                const float h1 = __uint_as_float(h & 0xFFFF0000u);
                Ahi32[b32 + j] = h;
                Alo32[b32 + j] = bf2pack(v1 - h1, v0 - h0);
            }
        }
        __syncthreads();

        // ---- MMA ----
        wmma::fragment<wmma::accumulator, 16, 16, 16, float> acc[2];
#pragma unroll
        for (int ti = 0; ti < 2; ti++) {
            const int t = wid * 2 + ti;
            wmma::fill_fragment(acc[ti], 0.0f);
            const __nv_bfloat16* At_hi = Ahi + t * (16 * ALD);
            const __nv_bfloat16* At_lo = Alo + t * (16 * ALD);
            wmma::fragment<wmma::matrix_a, 16, 16, 16, __nv_bfloat16, wmma::row_major> fah, fal;
#pragma unroll
            for (int kc = 0; kc < 2; kc++) {
                wmma::load_matrix_sync(fah, At_hi + kc * 16, ALD);
                wmma::load_matrix_sync(fal, At_lo + kc * 16, ALD);
                wmma::mma_sync(acc[ti], fah, fbh[kc], acc[ti]);
                wmma::mma_sync(acc[ti], fal, fbh[kc], acc[ti]);
                wmma::mma_sync(acc[ti], fah, fbl[kc], acc[ti]);
            }
        }
        __syncthreads();   // A reads done -> D may alias

#pragma unroll
        for (int ti = 0; ti < 2; ti++) {
            const int t = wid * 2 + ti;
            wmma::store_matrix_sync(Dsm + t * DTILE_F, acc[ti], DLD, wmma::mem_col_major);
        }
        __syncthreads();

        // ---- pool + bias' + clamp, float4 store ----
        {
            const int oc = u & 15, g = u >> 4;
            const float4* Dp = (const float4*)(Dsm + g * DTILE_F + oc * DLD);
            const float bsv = sbs[oc];
            float4 res;
            float* rr = &res.x;
#pragma unroll
            for (int i = 0; i < 4; i++) {
                const float4 qv = Dp[i];
                float mx = fmaxf(fmaxf(qv.x, qv.y), fmaxf(qv.z, qv.w));
                rr[i] = fminf(fmaxf(mx + bsv, 0.0f), 1.0f);
            }
            float* op = out + (((size_t)(bi * OCN + oc)) * PH + ph) * PW + pw0 + g * 4;
            *(float4*)op = res;
        }
    }
}

// ======================= launch =======================
static cudaStream_t g_s2 = nullptr;
static cudaEvent_t  g_ea = nullptr, g_eb = nullptr;

extern "C" void kernel_launch(void* const* d_in, const int* in_sizes, int n_in,
                              void* d_out, int out_size) {
    const float* x     = (const float*)d_in[0];
    const float* w     = (const float*)d_in[1];
    const float* bias  = (const float*)d_in[2];
    const float* scale = (const float*)d_in[3];
    float* out = (float*)d_out;

    const int B = in_sizes[0] / (ICN * IH * IW);   // 32

    if (!g_s2) {   // one-time infra init (first call is the non-capturing run)
        cudaStreamCreateWithFlags(&g_s2, cudaStreamNonBlocking);
        cudaEventCreateWithFlags(&g_ea, cudaEventDisableTiming);
        cudaEventCreateWithFlags(&g_eb, cudaEventDisableTiming);
    }

    // Work split: pooled rows [0, 2*GS) scalar, [2*GS, 256*B) wmma. alpha=0.8.
    const int phb_total = B * 128;
    const int GS = (phb_total * 4) / 5;            // 3276 for B=32
    const int scalar_units = GS * 8;
    const int r0 = 2 * GS;
    const int wmma_units = (B * 256 - r0) * 4;

    // fork: wmma on side stream
    cudaEventRecord(g_ea, 0);
    cudaStreamWaitEvent(g_s2, g_ea, 0);
    conv_wmma_kernel<<<WGRID, 256, 0, g_s2>>>(x, w, bias, scale, out, r0, wmma_units);
    cudaEventRecord(g_eb, g_s2);

    // scalar path on main stream
    prep_kernel<<<1, 512>>>(w, bias, scale);
    void* stage_ptr = nullptr;
    cudaGetSymbolAddress(&stage_ptr, g_stage);
    cudaMemcpyToSymbolAsync(c_p, stage_ptr, sizeof(Params), 0,
                            cudaMemcpyDeviceToDevice, 0);
    conv_scalar_kernel<<<SGRID, 128>>>(x, out, scalar_units);

    // join
    cudaStreamWaitEvent(0, g_eb, 0);
}